// round 2
// baseline (speedup 1.0000x reference)
#include <cuda_runtime.h>

#define BB 8
#define CC 256
#define HH 96
#define WW 96
#define HS 192
#define WS 192
#define OC 32
#define GG 4
#define CG 64   // CC/GG

typedef unsigned long long u64;

// Offset field scratch: [B][G][HS][WS] x float2 (x-offset, y-offset) interleaved
__device__ float g_off[BB * GG * HS * WS * 2];

#define FMA_F32X2(d, a, b) \
    asm("fma.rn.f32x2 %0, %1, %2, %0;" : "+l"(d) : "l"(a), "l"(b))
#define PACK_F32X2(out, lo, hi) \
    asm("mov.b64 %0, {%1, %2};" : "=l"(out) : "f"(lo), "f"(hi))
#define UNPACK_F32X2(lo, hi, in) \
    asm("mov.b64 {%0, %1}, %2;" : "=f"(lo), "=f"(hi) : "l"(in))

// ---------------------------------------------------------------------------
// Kernel 1: 1x1 conv (32 outputs over 256 channels) + tanh + pixel_shuffle(2)
// One thread = one low-res pixel. Accumulators are 16 packed f32x2 pairs;
// FMAs use fma.rn.f32x2 (FFMA2) to halve FMA instruction count.
// ---------------------------------------------------------------------------
__global__ __launch_bounds__(256) void conv_offset_kernel(
    const float* __restrict__ x, const float* __restrict__ w,
    const float* __restrict__ bias)
{
    __shared__ __align__(16) float wT[CC * OC];  // wT[c*32 + o]
    int tid = threadIdx.x;
    #pragma unroll
    for (int k = 0; k < (CC * OC) / 256; ++k) {
        int flat = tid + k * 256;
        int c = flat >> 5, o = flat & 31;
        wT[flat] = w[o * CC + c];
    }
    __syncthreads();

    int p   = blockIdx.x * 256 + tid;       // 0 .. B*H*W-1 (73728)
    int b   = p / (HH * WW);
    int rem = p - b * (HH * WW);
    int h   = rem / WW;
    int wp  = rem - h * WW;

    u64 acc[OC / 2];
    #pragma unroll
    for (int q = 0; q < OC / 2; ++q)
        PACK_F32X2(acc[q], bias[2 * q], bias[2 * q + 1]);

    const float* xp = x + (b * CC) * (HH * WW) + h * WW + wp;
    #pragma unroll 4
    for (int c = 0; c < CC; ++c) {
        float xv = __ldg(xp + c * (HH * WW));
        u64 xx;
        PACK_F32X2(xx, xv, xv);
        const ulonglong2* wrow = (const ulonglong2*)(wT + c * OC);
        #pragma unroll
        for (int q = 0; q < OC / 4; ++q) {
            ulonglong2 wv = wrow[q];          // LDS.128 = 2 f32x2 pairs
            FMA_F32X2(acc[2 * q + 0], xx, wv.x);
            FMA_F32X2(acc[2 * q + 1], xx, wv.y);
        }
    }

    // pixel_shuffle(2) + tanh + scatter into interleaved (x,y) offset field
    #pragma unroll
    for (int q = 0; q < OC / 2; ++q) {
        float a0, a1;
        UNPACK_F32X2(a0, a1, acc[q]);
        #pragma unroll
        for (int s = 0; s < 2; ++s) {
            int o    = 2 * q + s;
            float v  = tanhf(s ? a1 : a0);
            int co   = o >> 2;          // 0..7  channel after shuffle
            int i    = (o >> 1) & 1;    // row sub-position
            int j    = o & 1;           // col sub-position
            int gidx = co >> 1;         // group 0..3
            int k    = co & 1;          // 0 = x-offset, 1 = y-offset
            int hs = 2 * h + i, ws = 2 * wp + j;
            g_off[((((b * GG + gidx) * HS + hs) * WS + ws) << 1) + k] = v;
        }
    }
}

// ---------------------------------------------------------------------------
// Kernel 2: bilinear border grid_sample. One thread = 4 horizontally adjacent
// output pixels (same hs) -> STG.128 stores, 16 parallel LDGs per channel,
// index math amortized 4x over the 64-channel loop.
// ---------------------------------------------------------------------------
__global__ __launch_bounds__(256) void gather_kernel(
    const float* __restrict__ x, float* __restrict__ out)
{
    const int tiles = (HS * WS / 4) / 256;  // 36 quads-tiles per (b,g)
    int bg   = blockIdx.x / tiles;          // 0..31 = b*4 + gidx
    int tile = blockIdx.x - bg * tiles;
    int q    = tile * 256 + threadIdx.x;    // quad index 0..9215
    int hs   = q / (WS / 4);
    int wq   = q - hs * (WS / 4);
    int ws0  = 4 * wq;
    int b    = bg >> 2;
    int gidx = bg & 3;

    // 4 offset pairs (8 floats) = 2 x LDG.128
    const float4* offp = (const float4*)g_off + (((bg * HS + hs) * WS + ws0) >> 1);
    float4 oa = offp[0];   // (x0,y0,x1,y1)
    float4 ob = offp[1];   // (x2,y2,x3,y3)
    float offx[4] = {oa.x, oa.z, ob.x, ob.z};
    float offy[4] = {oa.y, oa.w, ob.y, ob.w};

    int   i00[4], dx[4], dy[4];
    float w00[4], w01[4], w10[4], w11[4];
    #pragma unroll
    for (int j = 0; j < 4; ++j) {
        // grid math collapsed: gx = (base_x + 0.125*off + 1)*48 - 0.5
        float gx = (float)(ws0 + j) * 0.5f - 0.25f + 6.0f * offx[j];
        float gy = (float)hs        * 0.5f - 0.25f + 6.0f * offy[j];
        gx = fminf(fmaxf(gx, 0.0f), (float)(WW - 1));
        gy = fminf(fmaxf(gy, 0.0f), (float)(HH - 1));
        int x0 = (int)gx;   // floor (gx >= 0)
        int y0 = (int)gy;
        float wx = gx - (float)x0;
        float wy = gy - (float)y0;
        dx[j]  = (x0 < WW - 1) ? 1  : 0;
        dy[j]  = (y0 < HH - 1) ? WW : 0;
        i00[j] = y0 * WW + x0;
        w00[j] = (1.0f - wx) * (1.0f - wy);
        w01[j] = wx * (1.0f - wy);
        w10[j] = (1.0f - wx) * wy;
        w11[j] = wx * wy;
    }

    const float* xp = x + (b * CC + gidx * CG) * (HH * WW);
    float*       op = out + ((b * CC + gidx * CG) * HS + hs) * WS + ws0;

    #pragma unroll 2
    for (int c = 0; c < CG; ++c) {
        float r[4];
        #pragma unroll
        for (int j = 0; j < 4; ++j) {
            float v00 = __ldg(xp + i00[j]);
            float v01 = __ldg(xp + i00[j] + dx[j]);
            float v10 = __ldg(xp + i00[j] + dy[j]);
            float v11 = __ldg(xp + i00[j] + dy[j] + dx[j]);
            r[j] = v00 * w00[j] + v01 * w01[j] + v10 * w10[j] + v11 * w11[j];
        }
        float4 res = {r[0], r[1], r[2], r[3]};
        *(float4*)op = res;
        xp += HH * WW;
        op += HS * WS;
    }
}

extern "C" void kernel_launch(void* const* d_in, const int* in_sizes, int n_in,
                              void* d_out, int out_size) {
    const float* x    = (const float*)d_in[0];
    const float* w    = (const float*)d_in[1];
    const float* bias = (const float*)d_in[2];
    float* out        = (float*)d_out;

    conv_offset_kernel<<<(BB * HH * WW) / 256, 256>>>(x, w, bias);
    gather_kernel<<<BB * GG * ((HS * WS / 4) / 256), 256>>>(x, out);
}